// round 16
// baseline (speedup 1.0000x reference)
#include <cuda_runtime.h>
#include <cstdint>

#define NN 100000
#define NE 3200000
#define NG 64

// Scratch (device globals). Values stored as int bit-patterns of nonnegative
// floats so signed-int atomicMax == float max (0 == 0.0f == identity of
// seg_max0+relu).
__device__ int d_h1[NN * 32];
__device__ int d_h2[NN * 32];
__device__ int d_pool[NG * 32];
__device__ int g_is64;   // 1 if index buffers are int64, 0 if int32

// ---------------- packed f32x2 helpers (sm_100+ PTX) ----------------
__device__ __forceinline__ unsigned long long dup2(float x) {
    unsigned long long r;
    asm("mov.b64 %0, {%1, %1};" : "=l"(r) : "f"(x));
    return r;
}
__device__ __forceinline__ unsigned long long pack2(float lo, float hi) {
    unsigned long long r;
    asm("mov.b64 %0, {%1, %2};" : "=l"(r) : "f"(lo), "f"(hi));
    return r;
}
__device__ __forceinline__ void unpack2(unsigned long long v, float& lo, float& hi) {
    asm("mov.b64 {%0, %1}, %2;" : "=f"(lo), "=f"(hi) : "l"(v));
}
__device__ __forceinline__ unsigned long long fma2(
    unsigned long long a, unsigned long long b, unsigned long long c) {
    unsigned long long d;
    asm("fma.rn.f32x2 %0, %1, %2, %3;" : "=l"(d) : "l"(a), "l"(b), "l"(c));
    return d;
}

// Uniform-branch index fetch honoring detected dtype.
__device__ __forceinline__ void load_edge(const void* ei, int e, int& src, int& dst) {
    if (g_is64) {
        const long long* p = (const long long*)ei;
        src = (int)p[e];
        dst = (int)p[NE + e];
    } else {
        const int* p = (const int*)ei;
        src = p[e];
        dst = p[NE + e];
    }
}
__device__ __forceinline__ int load_batch(const void* b, int n) {
    if (g_is64) return (int)((const long long*)b)[n];
    return ((const int*)b)[n];
}

// Epilogue helper: stale-read guard then atomic (monotone max => stale-safe).
__device__ __forceinline__ void max_update(int* addr, float v) {
    if (v > __int_as_float(*addr))
        atomicMax(addr, __float_as_int(v));
}

// ---------------- dtype probe ----------------
// int64 buffer of values in [0, 1e5) viewed as int32: odd words are all 0.
__global__ void detect_kernel(const int* __restrict__ ei32) {
    if (threadIdx.x == 0 && blockIdx.x == 0) {
        int all0 = 1;
#pragma unroll
        for (int i = 1; i < 64; i += 2)
            if (ei32[i] != 0) all0 = 0;
        g_is64 = all0;
    }
}

// ---------------- zero-init ----------------
__global__ void zero_kernel() {
    int i = blockIdx.x * blockDim.x + threadIdx.x;
    if (i < NN * 32) { d_h1[i] = 0; d_h2[i] = 0; }
    if (i < NG * 32) d_pool[i] = 0;
}

// ============ layer 1: pos(4) -> 32 -> 32, seg-max into d_h1 (EPT=2) ============
__global__ void __launch_bounds__(256) layer1_kernel(
    const float* __restrict__ pos,
    const float* __restrict__ w1a, const float* __restrict__ b1a,
    const float* __restrict__ w1b, const float* __restrict__ b1b,
    const void* __restrict__ ei)
{
    __shared__ __align__(16) float s_wa[4 * 32];   // [j][k] (k-pairs contiguous)
    __shared__ __align__(16) float s_ba[32];
    __shared__ __align__(16) float s_wbT[32 * 32]; // transposed: [c][k]
    __shared__ __align__(16) float s_bb[32];

    for (int i = threadIdx.x; i < 128; i += 256) s_wa[i] = w1a[i];
    if (threadIdx.x < 32) { s_ba[threadIdx.x] = b1a[threadIdx.x]; s_bb[threadIdx.x] = b1b[threadIdx.x]; }
    for (int i = threadIdx.x; i < 1024; i += 256) {
        int k = i >> 5, c = i & 31;
        s_wbT[c * 32 + k] = w1b[i];
    }
    __syncthreads();

    int e0 = blockIdx.x * 512 + threadIdx.x;   // NE % 512 == 0
    int e1 = e0 + 256;
    int src0, dst0, src1, dst1;
    load_edge(ei, e0, src0, dst0);
    load_edge(ei, e1, src1, dst1);

    float2 pj0 = __ldg((const float2*)pos + src0);
    float2 pi0 = __ldg((const float2*)pos + dst0);
    float2 pj1 = __ldg((const float2*)pos + src1);
    float2 pi1 = __ldg((const float2*)pos + dst1);
    float xs0[4] = { pj0.x, pj0.y, pj0.x - pi0.x, pj0.y - pi0.y };
    float xs1[4] = { pj1.x, pj1.y, pj1.x - pi1.x, pj1.y - pi1.y };

    // hidden = relu(x @ w1a + b1a), packed across output pairs, both edges
    unsigned long long acc0[16], acc1[16];
    {
        const ulonglong2* bp = (const ulonglong2*)s_ba;
#pragma unroll
        for (int q = 0; q < 8; q++) {
            ulonglong2 b2 = bp[q];
            acc0[2*q] = b2.x; acc0[2*q+1] = b2.y;
            acc1[2*q] = b2.x; acc1[2*q+1] = b2.y;
        }
    }
#pragma unroll
    for (int j = 0; j < 4; j++) {
        unsigned long long xd0 = dup2(xs0[j]);
        unsigned long long xd1 = dup2(xs1[j]);
        const ulonglong2* wp = (const ulonglong2*)&s_wa[j * 32];
#pragma unroll
        for (int q = 0; q < 8; q++) {
            ulonglong2 w = wp[q];                      // one LDS.128, two edges
            acc0[2*q]   = fma2(xd0, w.x, acc0[2*q]);
            acc0[2*q+1] = fma2(xd0, w.y, acc0[2*q+1]);
            acc1[2*q]   = fma2(xd1, w.x, acc1[2*q]);
            acc1[2*q+1] = fma2(xd1, w.y, acc1[2*q+1]);
        }
    }
#pragma unroll
    for (int k2 = 0; k2 < 16; k2++) {
        float lo, hi;
        unpack2(acc0[k2], lo, hi);
        acc0[k2] = pack2(fmaxf(lo, 0.0f), fmaxf(hi, 0.0f));
        unpack2(acc1[k2], lo, hi);
        acc1[k2] = pack2(fmaxf(lo, 0.0f), fmaxf(hi, 0.0f));
    }

    // m = hidden @ w1b + b1b; guarded atomic seg-max into d_h1[dst]
    int* outp0 = d_h1 + dst0 * 32;
    int* outp1 = d_h1 + dst1 * 32;
#pragma unroll
    for (int c = 0; c < 32; c++) {
        unsigned long long a20 = 0ull, a21 = 0ull;
        const ulonglong2* wr = (const ulonglong2*)&s_wbT[c * 32];
#pragma unroll
        for (int q = 0; q < 8; q++) {
            ulonglong2 w = wr[q];                      // one LDS.128, two edges
            a20 = fma2(acc0[2*q],   w.x, a20);
            a20 = fma2(acc0[2*q+1], w.y, a20);
            a21 = fma2(acc1[2*q],   w.x, a21);
            a21 = fma2(acc1[2*q+1], w.y, a21);
        }
        float lo, hi;
        unpack2(a20, lo, hi);
        max_update(&outp0[c], lo + hi + s_bb[c]);
        unpack2(a21, lo, hi);
        max_update(&outp1[c], lo + hi + s_bb[c]);
    }
}

// ============ layer 2: [h1(32), dpos(2)] -> 32 -> 32, seg-max into d_h2 (EPT=2) ============
__global__ void __launch_bounds__(256) layer2_kernel(
    const float* __restrict__ pos,
    const float* __restrict__ w2a, const float* __restrict__ b2a,
    const float* __restrict__ w2b, const float* __restrict__ b2b,
    const void* __restrict__ ei)
{
    __shared__ __align__(16) float s_wa[34 * 32];
    __shared__ __align__(16) float s_ba[32];
    __shared__ __align__(16) float s_wbT[32 * 32];
    __shared__ __align__(16) float s_bb[32];

    for (int i = threadIdx.x; i < 34 * 32; i += 256) s_wa[i] = w2a[i];
    if (threadIdx.x < 32) { s_ba[threadIdx.x] = b2a[threadIdx.x]; s_bb[threadIdx.x] = b2b[threadIdx.x]; }
    for (int i = threadIdx.x; i < 1024; i += 256) {
        int k = i >> 5, c = i & 31;
        s_wbT[c * 32 + k] = w2b[i];
    }
    __syncthreads();

    int e0 = blockIdx.x * 512 + threadIdx.x;
    int e1 = e0 + 256;
    int src0, dst0, src1, dst1;
    load_edge(ei, e0, src0, dst0);
    load_edge(ei, e1, src1, dst1);

    float2 pj0 = __ldg((const float2*)pos + src0);
    float2 pi0 = __ldg((const float2*)pos + dst0);
    float2 pj1 = __ldg((const float2*)pos + src1);
    float2 pi1 = __ldg((const float2*)pos + dst1);

    const float4* hp0 = (const float4*)(const void*)(d_h1 + src0 * 32);
    const float4* hp1 = (const float4*)(const void*)(d_h1 + src1 * 32);

    unsigned long long acc0[16], acc1[16];
    {
        const ulonglong2* bp = (const ulonglong2*)s_ba;
#pragma unroll
        for (int q = 0; q < 8; q++) {
            ulonglong2 b2 = bp[q];
            acc0[2*q] = b2.x; acc0[2*q+1] = b2.y;
            acc1[2*q] = b2.x; acc1[2*q+1] = b2.y;
        }
    }

    // h part: j = 0..31, streamed 4 features at a time (float4 gather)
#pragma unroll
    for (int g = 0; g < 8; g++) {
        float4 x0 = hp0[g];
        float4 x1 = hp1[g];
        float xe0[4] = { x0.x, x0.y, x0.z, x0.w };
        float xe1[4] = { x1.x, x1.y, x1.z, x1.w };
#pragma unroll
        for (int jj = 0; jj < 4; jj++) {
            unsigned long long xd0 = dup2(xe0[jj]);
            unsigned long long xd1 = dup2(xe1[jj]);
            const ulonglong2* wp = (const ulonglong2*)&s_wa[(4 * g + jj) * 32];
#pragma unroll
            for (int q = 0; q < 8; q++) {
                ulonglong2 w = wp[q];                  // one LDS.128, two edges
                acc0[2*q]   = fma2(xd0, w.x, acc0[2*q]);
                acc0[2*q+1] = fma2(xd0, w.y, acc0[2*q+1]);
                acc1[2*q]   = fma2(xd1, w.x, acc1[2*q]);
                acc1[2*q+1] = fma2(xd1, w.y, acc1[2*q+1]);
            }
        }
    }
    // dpos part: j = 32, 33
    {
        float d0[2] = { pj0.x - pi0.x, pj0.y - pi0.y };
        float d1[2] = { pj1.x - pi1.x, pj1.y - pi1.y };
#pragma unroll
        for (int jj = 0; jj < 2; jj++) {
            unsigned long long xd0 = dup2(d0[jj]);
            unsigned long long xd1 = dup2(d1[jj]);
            const ulonglong2* wp = (const ulonglong2*)&s_wa[(32 + jj) * 32];
#pragma unroll
            for (int q = 0; q < 8; q++) {
                ulonglong2 w = wp[q];
                acc0[2*q]   = fma2(xd0, w.x, acc0[2*q]);
                acc0[2*q+1] = fma2(xd0, w.y, acc0[2*q+1]);
                acc1[2*q]   = fma2(xd1, w.x, acc1[2*q]);
                acc1[2*q+1] = fma2(xd1, w.y, acc1[2*q+1]);
            }
        }
    }

#pragma unroll
    for (int k2 = 0; k2 < 16; k2++) {
        float lo, hi;
        unpack2(acc0[k2], lo, hi);
        acc0[k2] = pack2(fmaxf(lo, 0.0f), fmaxf(hi, 0.0f));
        unpack2(acc1[k2], lo, hi);
        acc1[k2] = pack2(fmaxf(lo, 0.0f), fmaxf(hi, 0.0f));
    }

    int* outp0 = d_h2 + dst0 * 32;
    int* outp1 = d_h2 + dst1 * 32;
#pragma unroll
    for (int c = 0; c < 32; c++) {
        unsigned long long a20 = 0ull, a21 = 0ull;
        const ulonglong2* wr = (const ulonglong2*)&s_wbT[c * 32];
#pragma unroll
        for (int q = 0; q < 8; q++) {
            ulonglong2 w = wr[q];                      // one LDS.128, two edges
            a20 = fma2(acc0[2*q],   w.x, a20);
            a20 = fma2(acc0[2*q+1], w.y, a20);
            a21 = fma2(acc1[2*q],   w.x, a21);
            a21 = fma2(acc1[2*q+1], w.y, a21);
        }
        float lo, hi;
        unpack2(a20, lo, hi);
        max_update(&outp0[c], lo + hi + s_bb[c]);
        unpack2(a21, lo, hi);
        max_update(&outp1[c], lo + hi + s_bb[c]);
    }
}

// ---------------- global max pool per graph (batch is sorted) ----------------
#define RLEN 128
#define NRANGES ((NN + RLEN - 1) / RLEN)   // 782
#define POOL_THREADS (NRANGES * 32)        // 25024

__global__ void pool_kernel(const void* __restrict__ batch) {
    int t = blockIdx.x * blockDim.x + threadIdx.x;
    if (t >= POOL_THREADS) return;
    int r = t >> 5;        // node range (warp-uniform)
    int c = t & 31;        // channel (lane)
    int n0 = r * RLEN;
    int n1 = min(n0 + RLEN, NN);

    int curg = load_batch(batch, n0);
    float curm = 0.0f;
    for (int n = n0; n < n1; n++) {
        int b = load_batch(batch, n);
        float v = __int_as_float(d_h2[n * 32 + c]);   // >= 0
        if (b != curg) {
            if (curm > 0.0f) atomicMax(&d_pool[curg * 32 + c], __float_as_int(curm));
            curg = b;
            curm = v;
        } else {
            curm = fmaxf(curm, v);
        }
    }
    if (curm > 0.0f) atomicMax(&d_pool[curg * 32 + c], __float_as_int(curm));
}

// ---------------- classifier: out[g] = pool[g] @ wc + bc ----------------
__global__ void final_kernel(const float* __restrict__ wc,
                             const float* __restrict__ bc,
                             float* __restrict__ out) {
    int t = threadIdx.x;
    if (t >= NG * 3) return;
    int g = t / 3, o = t % 3;
    float acc = bc[o];
#pragma unroll
    for (int cc = 0; cc < 32; cc++)
        acc += __int_as_float(d_pool[g * 32 + cc]) * wc[cc * 3 + o];
    out[t] = acc;
}

// ---------------- launch ----------------
extern "C" void kernel_launch(void* const* d_in, const int* in_sizes, int n_in,
                              void* d_out, int out_size) {
    const float* pos = (const float*)d_in[0];
    const float* w1a = (const float*)d_in[1];
    const float* b1a = (const float*)d_in[2];
    const float* w1b = (const float*)d_in[3];
    const float* b1b = (const float*)d_in[4];
    const float* w2a = (const float*)d_in[5];
    const float* b2a = (const float*)d_in[6];
    const float* w2b = (const float*)d_in[7];
    const float* b2b = (const float*)d_in[8];
    const float* wc  = (const float*)d_in[9];
    const float* bc  = (const float*)d_in[10];
    const void* ei    = d_in[11];
    const void* batch = d_in[12];

    detect_kernel<<<1, 32>>>((const int*)ei);
    zero_kernel<<<(NN * 32 + 255) / 256, 256>>>();
    layer1_kernel<<<NE / 512, 256>>>(pos, w1a, b1a, w1b, b1b, ei);
    layer2_kernel<<<NE / 512, 256>>>(pos, w2a, b2a, w2b, b2b, ei);
    pool_kernel<<<(POOL_THREADS + 255) / 256, 256>>>(batch);
    final_kernel<<<1, 192>>>(wc, bc, (float*)d_out);
}

// round 17
// speedup vs baseline: 1.0000x; 1.0000x over previous
#include <cuda_runtime.h>
#include <cstdint>

#define NN 100000
#define NE 3200000
#define NG 64

// Scratch (device globals). Values stored as int bit-patterns of nonnegative
// floats so signed-int atomicMax == float max (0 == 0.0f == identity of
// seg_max0+relu).
__device__ int d_h1[NN * 32];
__device__ int d_h2[NN * 32];
__device__ int d_pool[NG * 32];
__device__ int g_is64;   // 1 if index buffers are int64, 0 if int32

// ---------------- packed f32x2 helpers (sm_100+ PTX) ----------------
__device__ __forceinline__ unsigned long long dup2(float x) {
    unsigned long long r;
    asm("mov.b64 %0, {%1, %1};" : "=l"(r) : "f"(x));
    return r;
}
__device__ __forceinline__ unsigned long long pack2(float lo, float hi) {
    unsigned long long r;
    asm("mov.b64 %0, {%1, %2};" : "=l"(r) : "f"(lo), "f"(hi));
    return r;
}
__device__ __forceinline__ void unpack2(unsigned long long v, float& lo, float& hi) {
    asm("mov.b64 {%0, %1}, %2;" : "=f"(lo), "=f"(hi) : "l"(v));
}
__device__ __forceinline__ unsigned long long fma2(
    unsigned long long a, unsigned long long b, unsigned long long c) {
    unsigned long long d;
    asm("fma.rn.f32x2 %0, %1, %2, %3;" : "=l"(d) : "l"(a), "l"(b), "l"(c));
    return d;
}

// Uniform-branch index fetch honoring detected dtype.
__device__ __forceinline__ void load_edge(const void* ei, int e, int& src, int& dst) {
    if (g_is64) {
        const long long* p = (const long long*)ei;
        src = (int)p[e];
        dst = (int)p[NE + e];
    } else {
        const int* p = (const int*)ei;
        src = p[e];
        dst = p[NE + e];
    }
}
__device__ __forceinline__ int load_batch(const void* b, int n) {
    if (g_is64) return (int)((const long long*)b)[n];
    return ((const int*)b)[n];
}

// Epilogue helper: stale-read guard then atomic (monotone max => stale-safe).
__device__ __forceinline__ void max_update(int* addr, float v) {
    if (v > __int_as_float(*addr))
        atomicMax(addr, __float_as_int(v));
}

// ---------------- dtype probe ----------------
// int64 buffer of values in [0, 1e5) viewed as int32: odd words are all 0.
__global__ void detect_kernel(const int* __restrict__ ei32) {
    if (threadIdx.x == 0 && blockIdx.x == 0) {
        int all0 = 1;
#pragma unroll
        for (int i = 1; i < 64; i += 2)
            if (ei32[i] != 0) all0 = 0;
        g_is64 = all0;
    }
}

// ---------------- zero-init ----------------
__global__ void zero_kernel() {
    int i = blockIdx.x * blockDim.x + threadIdx.x;
    if (i < NN * 32) { d_h1[i] = 0; d_h2[i] = 0; }
    if (i < NG * 32) d_pool[i] = 0;
}

// ============ layer 1: pos(4) -> 32 -> 32, seg-max into d_h1 (EPT=2) ============
__global__ void __launch_bounds__(256) layer1_kernel(
    const float* __restrict__ pos,
    const float* __restrict__ w1a, const float* __restrict__ b1a,
    const float* __restrict__ w1b, const float* __restrict__ b1b,
    const void* __restrict__ ei)
{
    __shared__ __align__(16) float s_wa[4 * 32];   // [j][k] (k-pairs contiguous)
    __shared__ __align__(16) float s_ba[32];
    __shared__ __align__(16) float s_wbT[32 * 32]; // transposed: [c][k]
    __shared__ __align__(16) float s_bb[32];

    for (int i = threadIdx.x; i < 128; i += 256) s_wa[i] = w1a[i];
    if (threadIdx.x < 32) { s_ba[threadIdx.x] = b1a[threadIdx.x]; s_bb[threadIdx.x] = b1b[threadIdx.x]; }
    for (int i = threadIdx.x; i < 1024; i += 256) {
        int k = i >> 5, c = i & 31;
        s_wbT[c * 32 + k] = w1b[i];
    }
    __syncthreads();

    int e0 = blockIdx.x * 512 + threadIdx.x;   // NE % 512 == 0
    int e1 = e0 + 256;
    int src0, dst0, src1, dst1;
    load_edge(ei, e0, src0, dst0);
    load_edge(ei, e1, src1, dst1);

    float2 pj0 = __ldg((const float2*)pos + src0);
    float2 pi0 = __ldg((const float2*)pos + dst0);
    float2 pj1 = __ldg((const float2*)pos + src1);
    float2 pi1 = __ldg((const float2*)pos + dst1);
    float xs0[4] = { pj0.x, pj0.y, pj0.x - pi0.x, pj0.y - pi0.y };
    float xs1[4] = { pj1.x, pj1.y, pj1.x - pi1.x, pj1.y - pi1.y };

    // hidden = relu(x @ w1a + b1a), packed across output pairs, both edges
    unsigned long long acc0[16], acc1[16];
    {
        const ulonglong2* bp = (const ulonglong2*)s_ba;
#pragma unroll
        for (int q = 0; q < 8; q++) {
            ulonglong2 b2 = bp[q];
            acc0[2*q] = b2.x; acc0[2*q+1] = b2.y;
            acc1[2*q] = b2.x; acc1[2*q+1] = b2.y;
        }
    }
#pragma unroll
    for (int j = 0; j < 4; j++) {
        unsigned long long xd0 = dup2(xs0[j]);
        unsigned long long xd1 = dup2(xs1[j]);
        const ulonglong2* wp = (const ulonglong2*)&s_wa[j * 32];
#pragma unroll
        for (int q = 0; q < 8; q++) {
            ulonglong2 w = wp[q];                      // one LDS.128, two edges
            acc0[2*q]   = fma2(xd0, w.x, acc0[2*q]);
            acc0[2*q+1] = fma2(xd0, w.y, acc0[2*q+1]);
            acc1[2*q]   = fma2(xd1, w.x, acc1[2*q]);
            acc1[2*q+1] = fma2(xd1, w.y, acc1[2*q+1]);
        }
    }
#pragma unroll
    for (int k2 = 0; k2 < 16; k2++) {
        float lo, hi;
        unpack2(acc0[k2], lo, hi);
        acc0[k2] = pack2(fmaxf(lo, 0.0f), fmaxf(hi, 0.0f));
        unpack2(acc1[k2], lo, hi);
        acc1[k2] = pack2(fmaxf(lo, 0.0f), fmaxf(hi, 0.0f));
    }

    // m = hidden @ w1b + b1b; guarded atomic seg-max into d_h1[dst]
    int* outp0 = d_h1 + dst0 * 32;
    int* outp1 = d_h1 + dst1 * 32;
#pragma unroll
    for (int c = 0; c < 32; c++) {
        unsigned long long a20 = 0ull, a21 = 0ull;
        const ulonglong2* wr = (const ulonglong2*)&s_wbT[c * 32];
#pragma unroll
        for (int q = 0; q < 8; q++) {
            ulonglong2 w = wr[q];                      // one LDS.128, two edges
            a20 = fma2(acc0[2*q],   w.x, a20);
            a20 = fma2(acc0[2*q+1], w.y, a20);
            a21 = fma2(acc1[2*q],   w.x, a21);
            a21 = fma2(acc1[2*q+1], w.y, a21);
        }
        float lo, hi;
        unpack2(a20, lo, hi);
        max_update(&outp0[c], lo + hi + s_bb[c]);
        unpack2(a21, lo, hi);
        max_update(&outp1[c], lo + hi + s_bb[c]);
    }
}

// ============ layer 2: [h1(32), dpos(2)] -> 32 -> 32, seg-max into d_h2 (EPT=2) ============
__global__ void __launch_bounds__(256) layer2_kernel(
    const float* __restrict__ pos,
    const float* __restrict__ w2a, const float* __restrict__ b2a,
    const float* __restrict__ w2b, const float* __restrict__ b2b,
    const void* __restrict__ ei)
{
    __shared__ __align__(16) float s_wa[34 * 32];
    __shared__ __align__(16) float s_ba[32];
    __shared__ __align__(16) float s_wbT[32 * 32];
    __shared__ __align__(16) float s_bb[32];

    for (int i = threadIdx.x; i < 34 * 32; i += 256) s_wa[i] = w2a[i];
    if (threadIdx.x < 32) { s_ba[threadIdx.x] = b2a[threadIdx.x]; s_bb[threadIdx.x] = b2b[threadIdx.x]; }
    for (int i = threadIdx.x; i < 1024; i += 256) {
        int k = i >> 5, c = i & 31;
        s_wbT[c * 32 + k] = w2b[i];
    }
    __syncthreads();

    int e0 = blockIdx.x * 512 + threadIdx.x;
    int e1 = e0 + 256;
    int src0, dst0, src1, dst1;
    load_edge(ei, e0, src0, dst0);
    load_edge(ei, e1, src1, dst1);

    float2 pj0 = __ldg((const float2*)pos + src0);
    float2 pi0 = __ldg((const float2*)pos + dst0);
    float2 pj1 = __ldg((const float2*)pos + src1);
    float2 pi1 = __ldg((const float2*)pos + dst1);

    const float4* hp0 = (const float4*)(const void*)(d_h1 + src0 * 32);
    const float4* hp1 = (const float4*)(const void*)(d_h1 + src1 * 32);

    unsigned long long acc0[16], acc1[16];
    {
        const ulonglong2* bp = (const ulonglong2*)s_ba;
#pragma unroll
        for (int q = 0; q < 8; q++) {
            ulonglong2 b2 = bp[q];
            acc0[2*q] = b2.x; acc0[2*q+1] = b2.y;
            acc1[2*q] = b2.x; acc1[2*q+1] = b2.y;
        }
    }

    // h part: j = 0..31, streamed 4 features at a time (float4 gather)
#pragma unroll
    for (int g = 0; g < 8; g++) {
        float4 x0 = hp0[g];
        float4 x1 = hp1[g];
        float xe0[4] = { x0.x, x0.y, x0.z, x0.w };
        float xe1[4] = { x1.x, x1.y, x1.z, x1.w };
#pragma unroll
        for (int jj = 0; jj < 4; jj++) {
            unsigned long long xd0 = dup2(xe0[jj]);
            unsigned long long xd1 = dup2(xe1[jj]);
            const ulonglong2* wp = (const ulonglong2*)&s_wa[(4 * g + jj) * 32];
#pragma unroll
            for (int q = 0; q < 8; q++) {
                ulonglong2 w = wp[q];                  // one LDS.128, two edges
                acc0[2*q]   = fma2(xd0, w.x, acc0[2*q]);
                acc0[2*q+1] = fma2(xd0, w.y, acc0[2*q+1]);
                acc1[2*q]   = fma2(xd1, w.x, acc1[2*q]);
                acc1[2*q+1] = fma2(xd1, w.y, acc1[2*q+1]);
            }
        }
    }
    // dpos part: j = 32, 33
    {
        float d0[2] = { pj0.x - pi0.x, pj0.y - pi0.y };
        float d1[2] = { pj1.x - pi1.x, pj1.y - pi1.y };
#pragma unroll
        for (int jj = 0; jj < 2; jj++) {
            unsigned long long xd0 = dup2(d0[jj]);
            unsigned long long xd1 = dup2(d1[jj]);
            const ulonglong2* wp = (const ulonglong2*)&s_wa[(32 + jj) * 32];
#pragma unroll
            for (int q = 0; q < 8; q++) {
                ulonglong2 w = wp[q];
                acc0[2*q]   = fma2(xd0, w.x, acc0[2*q]);
                acc0[2*q+1] = fma2(xd0, w.y, acc0[2*q+1]);
                acc1[2*q]   = fma2(xd1, w.x, acc1[2*q]);
                acc1[2*q+1] = fma2(xd1, w.y, acc1[2*q+1]);
            }
        }
    }

#pragma unroll
    for (int k2 = 0; k2 < 16; k2++) {
        float lo, hi;
        unpack2(acc0[k2], lo, hi);
        acc0[k2] = pack2(fmaxf(lo, 0.0f), fmaxf(hi, 0.0f));
        unpack2(acc1[k2], lo, hi);
        acc1[k2] = pack2(fmaxf(lo, 0.0f), fmaxf(hi, 0.0f));
    }

    int* outp0 = d_h2 + dst0 * 32;
    int* outp1 = d_h2 + dst1 * 32;
#pragma unroll
    for (int c = 0; c < 32; c++) {
        unsigned long long a20 = 0ull, a21 = 0ull;
        const ulonglong2* wr = (const ulonglong2*)&s_wbT[c * 32];
#pragma unroll
        for (int q = 0; q < 8; q++) {
            ulonglong2 w = wr[q];                      // one LDS.128, two edges
            a20 = fma2(acc0[2*q],   w.x, a20);
            a20 = fma2(acc0[2*q+1], w.y, a20);
            a21 = fma2(acc1[2*q],   w.x, a21);
            a21 = fma2(acc1[2*q+1], w.y, a21);
        }
        float lo, hi;
        unpack2(a20, lo, hi);
        max_update(&outp0[c], lo + hi + s_bb[c]);
        unpack2(a21, lo, hi);
        max_update(&outp1[c], lo + hi + s_bb[c]);
    }
}

// ---------------- global max pool per graph (batch is sorted) ----------------
#define RLEN 128
#define NRANGES ((NN + RLEN - 1) / RLEN)   // 782
#define POOL_THREADS (NRANGES * 32)        // 25024

__global__ void pool_kernel(const void* __restrict__ batch) {
    int t = blockIdx.x * blockDim.x + threadIdx.x;
    if (t >= POOL_THREADS) return;
    int r = t >> 5;        // node range (warp-uniform)
    int c = t & 31;        // channel (lane)
    int n0 = r * RLEN;
    int n1 = min(n0 + RLEN, NN);

    int curg = load_batch(batch, n0);
    float curm = 0.0f;
    for (int n = n0; n < n1; n++) {
        int b = load_batch(batch, n);
        float v = __int_as_float(d_h2[n * 32 + c]);   // >= 0
        if (b != curg) {
            if (curm > 0.0f) atomicMax(&d_pool[curg * 32 + c], __float_as_int(curm));
            curg = b;
            curm = v;
        } else {
            curm = fmaxf(curm, v);
        }
    }
    if (curm > 0.0f) atomicMax(&d_pool[curg * 32 + c], __float_as_int(curm));
}

// ---------------- classifier: out[g] = pool[g] @ wc + bc ----------------
__global__ void final_kernel(const float* __restrict__ wc,
                             const float* __restrict__ bc,
                             float* __restrict__ out) {
    int t = threadIdx.x;
    if (t >= NG * 3) return;
    int g = t / 3, o = t % 3;
    float acc = bc[o];
#pragma unroll
    for (int cc = 0; cc < 32; cc++)
        acc += __int_as_float(d_pool[g * 32 + cc]) * wc[cc * 3 + o];
    out[t] = acc;
}

// ---------------- launch ----------------
extern "C" void kernel_launch(void* const* d_in, const int* in_sizes, int n_in,
                              void* d_out, int out_size) {
    const float* pos = (const float*)d_in[0];
    const float* w1a = (const float*)d_in[1];
    const float* b1a = (const float*)d_in[2];
    const float* w1b = (const float*)d_in[3];
    const float* b1b = (const float*)d_in[4];
    const float* w2a = (const float*)d_in[5];
    const float* b2a = (const float*)d_in[6];
    const float* w2b = (const float*)d_in[7];
    const float* b2b = (const float*)d_in[8];
    const float* wc  = (const float*)d_in[9];
    const float* bc  = (const float*)d_in[10];
    const void* ei    = d_in[11];
    const void* batch = d_in[12];

    detect_kernel<<<1, 32>>>((const int*)ei);
    zero_kernel<<<(NN * 32 + 255) / 256, 256>>>();
    layer1_kernel<<<NE / 512, 256>>>(pos, w1a, b1a, w1b, b1b, ei);
    layer2_kernel<<<NE / 512, 256>>>(pos, w2a, b2a, w2b, b2b, ei);
    pool_kernel<<<(POOL_THREADS + 255) / 256, 256>>>(batch);
    final_kernel<<<1, 192>>>(wc, bc, (float*)d_out);
}